// round 10
// baseline (speedup 1.0000x reference)
#include <cuda_runtime.h>
#include <math.h>
#include <stdint.h>

#define MAX_E 3200000
#define MAX_N 100000
#define FIN 128
#define H1D 64
#define H2D 32
#define NCLS 10
#define SCAN_B 512
#define MAX_BLKS ((MAX_N + SCAN_B) / SCAN_B + 2)

// ---------------- scratch (device globals; referenced directly, no host APIs)
__device__ __align__(16) int   g_indeg[MAX_N];
__device__ __align__(16) int   g_off[MAX_N + 1];
__device__ __align__(16) int   g_pos[MAX_N];
__device__ __align__(16) int   g_part[MAX_N];
__device__ __align__(16) int   g_bsum[MAX_BLKS];
__device__ __align__(16) float g_dinv[MAX_N];
__device__ __align__(16) int   g_esrc[MAX_E];
__device__ __align__(16) float g_enorm[MAX_E];
__device__ __align__(16) float g_h1[MAX_N * H1D];
__device__ __align__(16) float g_a1[MAX_N * H1D];
__device__ __align__(16) float g_h2[MAX_N * H2D];

// ---------------- CSR build ---------------------------------------------------
__global__ void k_zero(int N) {
    int i = blockIdx.x * blockDim.x + threadIdx.x;
    if (i < N) g_indeg[i] = 0;
}

// edge_index is int32 (JAX default x64-disabled): row 0 = src, row 1 = dst
__global__ void k_count(const int* __restrict__ ei, int E) {
    int e = blockIdx.x * blockDim.x + threadIdx.x;
    if (e >= E) return;
    atomicAdd(&g_indeg[ei[e + E]], 1);
}

__global__ void k_scan1(int N) {
    __shared__ int sm[SCAN_B];
    int gid = blockIdx.x * SCAN_B + threadIdx.x;
    int v = (gid < N) ? g_indeg[gid] : 0;
    sm[threadIdx.x] = v;
    __syncthreads();
#pragma unroll
    for (int s = 1; s < SCAN_B; s <<= 1) {
        int t = (threadIdx.x >= (unsigned)s) ? sm[threadIdx.x - s] : 0;
        __syncthreads();
        sm[threadIdx.x] += t;
        __syncthreads();
    }
    if (gid < N) g_part[gid] = sm[threadIdx.x] - v;  // exclusive within block
    if (threadIdx.x == SCAN_B - 1) g_bsum[blockIdx.x] = sm[threadIdx.x];
}

// parallel exclusive scan of block sums (nb <= 256)
__global__ void k_scan2(int nb) {
    __shared__ int sm[256];
    int t = threadIdx.x;
    int v = (t < nb) ? g_bsum[t] : 0;
    sm[t] = v;
    __syncthreads();
#pragma unroll
    for (int s = 1; s < 256; s <<= 1) {
        int u = (t >= (unsigned)s) ? sm[t - s] : 0;
        __syncthreads();
        sm[t] += u;
        __syncthreads();
    }
    if (t < nb) g_bsum[t] = sm[t] - v;  // exclusive
}

__global__ void k_scan3(int N, int E) {
    int gid = blockIdx.x * blockDim.x + threadIdx.x;
    if (gid < N) {
        int o = g_part[gid] + g_bsum[gid / SCAN_B];
        g_off[gid] = o;
        g_pos[gid] = o;
    }
    if (gid == 0) g_off[N] = E;
}

__global__ void k_dinv(int N) {
    int i = blockIdx.x * blockDim.x + threadIdx.x;
    if (i < N) g_dinv[i] = rsqrtf((float)g_indeg[i] + 1.0f);
}

__global__ void k_fill(const int* __restrict__ ei, int E) {
    int e = blockIdx.x * blockDim.x + threadIdx.x;
    if (e >= E) return;
    int s = ei[e];
    int d = ei[e + E];
    int p = atomicAdd(&g_pos[d], 1);
    g_esrc[p]  = s;
    g_enorm[p] = g_dinv[s] * g_dinv[d];
}

// ---------------- dense GEMM: out[N,ODIM] = (relu?)X[N,KDIM] @ W[KDIM,ODIM] --
// LAYER 1: X = feat param, out = g_h1. LAYER 2: X = g_a1, out = g_h2.
template <int KDIM, int ODIM, bool RELU_IN, int LAYER>
__global__ void k_gemm(const float* __restrict__ Xparam, const float* __restrict__ Wg,
                       int N) {
    const float* X  = (LAYER == 1) ? Xparam : g_a1;
    float*      out = (LAYER == 1) ? g_h1   : g_h2;

    constexpr int NL  = 256 / ODIM;   // row-lanes
    constexpr int RPT = 4;            // rows per thread
    constexpr int RPB = NL * RPT;     // rows per block
    __shared__ float Wsm[KDIM * ODIM];
    __shared__ float Xsm[RPB * KDIM];

    int tid = threadIdx.x;
    for (int i = tid; i < KDIM * ODIM; i += 256) Wsm[i] = Wg[i];

    int row0 = blockIdx.x * RPB;
    for (int i = tid; i < RPB * KDIM; i += 256) {
        int r = i / KDIM, k = i - r * KDIM;
        int gr = row0 + r;
        float v = (gr < N) ? X[(size_t)gr * KDIM + k] : 0.0f;
        if (RELU_IN) v = fmaxf(v, 0.0f);
        Xsm[i] = v;
    }
    __syncthreads();

    int col = tid % ODIM;
    int rl  = tid / ODIM;
    float acc[RPT];
#pragma unroll
    for (int j = 0; j < RPT; j++) acc[j] = 0.0f;

#pragma unroll 4
    for (int k = 0; k < KDIM; k++) {
        float w = Wsm[k * ODIM + col];
#pragma unroll
        for (int j = 0; j < RPT; j++)
            acc[j] += Xsm[(rl * RPT + j) * KDIM + k] * w;
    }
#pragma unroll
    for (int j = 0; j < RPT; j++) {
        int gr = row0 + rl * RPT + j;
        if (gr < N) out[(size_t)gr * ODIM + col] = acc[j];
    }
}

// -------- CSR gather layer 1 (F=64): float2 per lane (R9-proven) -------------
// a1[i] = sum_j h1[src_j]*norm_j + h1[i]*dinv[i]^2 + b1
__global__ void k_gather64(const float* __restrict__ b, int N) {
    const float2* h = (const float2*)g_h1;
    float2*     out = (float2*)g_a1;
    constexpr int C2 = H1D / 2;   // 32 float2 per row: one per lane

    int node = blockIdx.x * (blockDim.x >> 5) + (threadIdx.x >> 5);
    int lane = threadIdx.x & 31;
    if (node >= N) return;

    int beg = g_off[node];
    int end = g_off[node + 1];

    float ax = 0.0f, ay = 0.0f;
    int j = beg;
    for (; j + 1 < end; j += 2) {          // 2-edge pipeline for MLP
        int   s0 = __ldg(&g_esrc[j]);
        int   s1 = __ldg(&g_esrc[j + 1]);
        float n0 = __ldg(&g_enorm[j]);
        float n1 = __ldg(&g_enorm[j + 1]);
        float2 v0 = __ldg(&h[(size_t)s0 * C2 + lane]);
        float2 v1 = __ldg(&h[(size_t)s1 * C2 + lane]);
        ax += v0.x * n0 + v1.x * n1;
        ay += v0.y * n0 + v1.y * n1;
    }
    if (j < end) {
        int   s0 = __ldg(&g_esrc[j]);
        float n0 = __ldg(&g_enorm[j]);
        float2 v0 = __ldg(&h[(size_t)s0 * C2 + lane]);
        ax += v0.x * n0;
        ay += v0.y * n0;
    }

    float di = g_dinv[node];
    float d2 = di * di;
    float2 hv = h[(size_t)node * C2 + lane];
    float2 bv = ((const float2*)b)[lane];
    float2 o;
    o.x = ax + hv.x * d2 + bv.x;
    o.y = ay + hv.y * d2 + bv.y;
    out[(size_t)node * C2 + lane] = o;
}

// -------- CSR gather layer 2 (F=32) + relu + classifier + log_softmax --------
// One warp per node, lane = feature column. Fused epilogue (kills k_final +
// the g_a2 round-trip).
__global__ void k_gather32f(const float* __restrict__ b, const float* __restrict__ Wc,
                            const float* __restrict__ bc, float* __restrict__ outp,
                            int N) {
    constexpr int F = H2D;
    __shared__ float WcSm[H2D * NCLS];
    __shared__ float bcSm[NCLS];
    int tid = threadIdx.x;
    for (int i = tid; i < H2D * NCLS; i += blockDim.x) WcSm[i] = Wc[i];
    if (tid < NCLS) bcSm[tid] = bc[tid];
    __syncthreads();

    int node = blockIdx.x * (blockDim.x >> 5) + (tid >> 5);
    int lane = tid & 31;
    if (node >= N) return;  // warp-uniform exit

    const float* h = g_h2;
    int beg = g_off[node];
    int end = g_off[node + 1];

    float acc = 0.0f;
    int j = beg;
    for (; j + 1 < end; j += 2) {
        int   s0 = __ldg(&g_esrc[j]);
        int   s1 = __ldg(&g_esrc[j + 1]);
        float n0 = __ldg(&g_enorm[j]);
        float n1 = __ldg(&g_enorm[j + 1]);
        acc += __ldg(&h[(size_t)s0 * F + lane]) * n0;
        acc += __ldg(&h[(size_t)s1 * F + lane]) * n1;
    }
    if (j < end) {
        int   s0 = __ldg(&g_esrc[j]);
        float n0 = __ldg(&g_enorm[j]);
        acc += __ldg(&h[(size_t)s0 * F + lane]) * n0;
    }

    float di = g_dinv[node];
    float x = acc + h[(size_t)node * F + lane] * di * di + b[lane];
    x = fmaxf(x, 0.0f);  // relu before classifier

    // logits: lg[c] = sum_lane x * Wc[lane][c]  (warp butterfly on 10-vector)
    float p[NCLS];
#pragma unroll
    for (int c = 0; c < NCLS; c++) p[c] = x * WcSm[lane * NCLS + c];
#pragma unroll
    for (int s = 16; s > 0; s >>= 1)
#pragma unroll
        for (int c = 0; c < NCLS; c++)
            p[c] += __shfl_xor_sync(0xffffffffu, p[c], s);

    float lg[NCLS];
#pragma unroll
    for (int c = 0; c < NCLS; c++) lg[c] = p[c] + bcSm[c];
    float mx = lg[0];
#pragma unroll
    for (int c = 1; c < NCLS; c++) mx = fmaxf(mx, lg[c]);
    float sum = 0.0f;
#pragma unroll
    for (int c = 0; c < NCLS; c++) sum += __expf(lg[c] - mx);
    float lse = mx + logf(sum);

    if (lane < NCLS) outp[(size_t)node * NCLS + lane] = lg[lane] - lse;
}

// ---------------- launch (kernel launches ONLY; graph-capture clean) ---------
extern "C" void kernel_launch(void* const* d_in, const int* in_sizes, int n_in,
                              void* d_out, int out_size) {
    const float* feat = (const float*)d_in[0];
    const int*   ei   = (const int*)d_in[1];    // int32! (JAX x64 disabled)
    const float* W1   = (const float*)d_in[2];
    const float* b1   = (const float*)d_in[3];
    const float* W2   = (const float*)d_in[4];
    const float* b2   = (const float*)d_in[5];
    const float* Wc   = (const float*)d_in[6];
    const float* bc   = (const float*)d_in[7];

    int N = in_sizes[0] / FIN;
    int E = in_sizes[1] / 2;

    const int T = 256;
    int nb = (N + SCAN_B - 1) / SCAN_B;

    // CSR build (gemm1 moved to slot 4 so ncu's capture window profiles it)
    k_zero<<<(N + T - 1) / T, T>>>(N);
    k_count<<<(E + T - 1) / T, T>>>(ei, E);
    k_scan1<<<nb, SCAN_B>>>(N);
    k_gemm<FIN, H1D, false, 1><<<(N + 15) / 16, 256>>>(feat, W1, N);  // launch #4
    k_scan2<<<1, 256>>>(nb);
    k_scan3<<<(N + T - 1) / T, T>>>(N, E);
    k_dinv<<<(N + T - 1) / T, T>>>(N);
    k_fill<<<(E + T - 1) / T, T>>>(ei, E);

    // layer 1 aggregation
    k_gather64<<<(N + 7) / 8, 256>>>(b1, N);

    // layer 2 + fused classifier/log_softmax
    k_gemm<H1D, H2D, true, 2><<<(N + 31) / 32, 256>>>(nullptr, W2, N);
    k_gather32f<<<(N + 7) / 8, 256>>>(b2, Wc, bc, (float*)d_out, N);
}

// round 11
// speedup vs baseline: 1.1295x; 1.1295x over previous
#include <cuda_runtime.h>
#include <math.h>
#include <stdint.h>

#define MAX_E 3200000
#define MAX_N 100000
#define FIN 128
#define H1D 64
#define H2D 32
#define NCLS 10
#define SCAN_B 512
#define MAX_BLKS ((MAX_N + SCAN_B) / SCAN_B + 2)

// ---------------- scratch (device globals; referenced directly, no host APIs)
__device__ __align__(16) int   g_indeg[MAX_N];
__device__ __align__(16) int   g_off[MAX_N + 1];
__device__ __align__(16) int   g_pos[MAX_N];
__device__ __align__(16) int   g_part[MAX_N];
__device__ __align__(16) int   g_bsum[MAX_BLKS];
__device__ __align__(16) float g_dinv[MAX_N];
__device__ __align__(16) int   g_esrc[MAX_E];
__device__ __align__(16) float g_enorm[MAX_E];
__device__ __align__(16) float g_h1[MAX_N * H1D];
__device__ __align__(16) float g_a1[MAX_N * H1D];
__device__ __align__(16) float g_h2[MAX_N * H2D];

// ---------------- f32x2 helpers ----------------------------------------------
__device__ __forceinline__ uint64_t pk2(float lo, float hi) {
    uint64_t r; asm("mov.b64 %0, {%1,%2};" : "=l"(r) : "f"(lo), "f"(hi)); return r;
}
__device__ __forceinline__ void upk2(uint64_t v, float& lo, float& hi) {
    asm("mov.b64 {%0,%1}, %2;" : "=f"(lo), "=f"(hi) : "l"(v));
}
__device__ __forceinline__ void fma2(uint64_t& d, uint64_t a, uint64_t b) {
    asm("fma.rn.f32x2 %0, %1, %2, %0;" : "+l"(d) : "l"(a), "l"(b));
}

// ---------------- CSR build ---------------------------------------------------
__global__ void k_zero(int N) {
    int i = blockIdx.x * blockDim.x + threadIdx.x;
    if (i < N) g_indeg[i] = 0;
}

__global__ void k_count(const int* __restrict__ ei, int E) {
    int e = blockIdx.x * blockDim.x + threadIdx.x;
    if (e >= E) return;
    atomicAdd(&g_indeg[ei[e + E]], 1);
}

__global__ void k_scan1(int N) {
    __shared__ int sm[SCAN_B];
    int gid = blockIdx.x * SCAN_B + threadIdx.x;
    int v = (gid < N) ? g_indeg[gid] : 0;
    sm[threadIdx.x] = v;
    __syncthreads();
#pragma unroll
    for (int s = 1; s < SCAN_B; s <<= 1) {
        int t = (threadIdx.x >= (unsigned)s) ? sm[threadIdx.x - s] : 0;
        __syncthreads();
        sm[threadIdx.x] += t;
        __syncthreads();
    }
    if (gid < N) g_part[gid] = sm[threadIdx.x] - v;
    if (threadIdx.x == SCAN_B - 1) g_bsum[blockIdx.x] = sm[threadIdx.x];
}

__global__ void k_scan2(int nb) {
    __shared__ int sm[256];
    int t = threadIdx.x;
    int v = (t < nb) ? g_bsum[t] : 0;
    sm[t] = v;
    __syncthreads();
#pragma unroll
    for (int s = 1; s < 256; s <<= 1) {
        int u = (t >= (unsigned)s) ? sm[t - s] : 0;
        __syncthreads();
        sm[t] += u;
        __syncthreads();
    }
    if (t < nb) g_bsum[t] = sm[t] - v;
}

__global__ void k_scan3(int N, int E) {
    int gid = blockIdx.x * blockDim.x + threadIdx.x;
    if (gid < N) {
        int o = g_part[gid] + g_bsum[gid / SCAN_B];
        g_off[gid] = o;
        g_pos[gid] = o;
    }
    if (gid == 0) g_off[N] = E;
}

__global__ void k_dinv(int N) {
    int i = blockIdx.x * blockDim.x + threadIdx.x;
    if (i < N) g_dinv[i] = rsqrtf((float)g_indeg[i] + 1.0f);
}

__global__ void k_fill(const int* __restrict__ ei, int E) {
    int e = blockIdx.x * blockDim.x + threadIdx.x;
    if (e >= E) return;
    int s = ei[e];
    int d = ei[e + E];
    int p = atomicAdd(&g_pos[d], 1);
    g_esrc[p]  = s;
    g_enorm[p] = g_dinv[s] * g_dinv[d];
}

// ---------------- f32x2 GEMM: out = (relu?)X @ W ------------------------------
// 256 threads; thread tile 4 rows x 8 cols (4 f32x2 accs per row).
// Xs transposed [k][row] (1 LDS.128 = 4 rows), Ws [k][col] (native f32x2 pairs).
template <int KDIM, int ODIM, bool RELU_IN, int LAYER>
__global__ void k_gemm2x(const float* __restrict__ Xparam, const float* __restrict__ Wg,
                         int N) {
    constexpr int KC   = 32;          // k-chunk
    constexpr int COLG = ODIM / 8;    // col groups
    constexpr int ROWG = 256 / COLG;  // row groups
    constexpr int TM   = ROWG * 4;    // rows per block
    constexpr int XP   = TM + 4;      // padded row stride (keeps 16B align)

    const float* X  = (LAYER == 1) ? Xparam : g_a1;
    float*      out = (LAYER == 1) ? g_h1   : g_h2;

    __shared__ float Xs[KC][XP];
    __shared__ float Ws[KC][ODIM];

    int tid  = threadIdx.x;
    int row0 = blockIdx.x * TM;
    int tx = tid % COLG, ty = tid / COLG;
    int c0 = tx * 8, r0 = ty * 4;

    uint64_t acc[4][4];
#pragma unroll
    for (int r = 0; r < 4; r++)
#pragma unroll
        for (int p = 0; p < 4; p++) acc[r][p] = 0ULL;

    for (int k0 = 0; k0 < KDIM; k0 += KC) {
        __syncthreads();
        // W chunk: contiguous KC*ODIM floats
        {
            const float4* src = (const float4*)(Wg + (size_t)k0 * ODIM);
            float4* dst = (float4*)&Ws[0][0];
            for (int i = tid; i < KC * ODIM / 4; i += 256) dst[i] = src[i];
        }
        // X chunk, transposed into Xs[k][row]
        for (int i = tid; i < TM * (KC / 4); i += 256) {
            int r = i / (KC / 4);
            int q = i - r * (KC / 4);
            int gr = row0 + r;
            float4 v = make_float4(0.f, 0.f, 0.f, 0.f);
            if (gr < N) v = *(const float4*)(X + (size_t)gr * KDIM + k0 + q * 4);
            if (RELU_IN) {
                v.x = fmaxf(v.x, 0.f); v.y = fmaxf(v.y, 0.f);
                v.z = fmaxf(v.z, 0.f); v.w = fmaxf(v.w, 0.f);
            }
            Xs[q * 4 + 0][r] = v.x;
            Xs[q * 4 + 1][r] = v.y;
            Xs[q * 4 + 2][r] = v.z;
            Xs[q * 4 + 3][r] = v.w;
        }
        __syncthreads();

#pragma unroll 8
        for (int k = 0; k < KC; k++) {
            float4 xv = *(const float4*)&Xs[k][r0];
            ulonglong2 wa = *(const ulonglong2*)&Ws[k][c0];
            ulonglong2 wb = *(const ulonglong2*)&Ws[k][c0 + 4];
            uint64_t wp[4] = {wa.x, wa.y, wb.x, wb.y};
            uint64_t xb[4] = {pk2(xv.x, xv.x), pk2(xv.y, xv.y),
                              pk2(xv.z, xv.z), pk2(xv.w, xv.w)};
#pragma unroll
            for (int r = 0; r < 4; r++)
#pragma unroll
                for (int p = 0; p < 4; p++) fma2(acc[r][p], xb[r], wp[p]);
        }
    }

#pragma unroll
    for (int r = 0; r < 4; r++) {
        int gr = row0 + r0 + r;
        if (gr >= N) continue;
        float4 o0, o1;
        upk2(acc[r][0], o0.x, o0.y); upk2(acc[r][1], o0.z, o0.w);
        upk2(acc[r][2], o1.x, o1.y); upk2(acc[r][3], o1.z, o1.w);
        float4* dst = (float4*)(out + (size_t)gr * ODIM + c0);
        dst[0] = o0;
        dst[1] = o1;
    }
}

// -------- CSR gather layer 1 (F=64): float2 per lane (R9-proven) -------------
__global__ void k_gather64(const float* __restrict__ b, int N) {
    const float2* h = (const float2*)g_h1;
    float2*     out = (float2*)g_a1;
    constexpr int C2 = H1D / 2;

    int node = blockIdx.x * (blockDim.x >> 5) + (threadIdx.x >> 5);
    int lane = threadIdx.x & 31;
    if (node >= N) return;

    int beg = g_off[node];
    int end = g_off[node + 1];

    float ax = 0.0f, ay = 0.0f;
    int j = beg;
    for (; j + 1 < end; j += 2) {
        int   s0 = __ldg(&g_esrc[j]);
        int   s1 = __ldg(&g_esrc[j + 1]);
        float n0 = __ldg(&g_enorm[j]);
        float n1 = __ldg(&g_enorm[j + 1]);
        float2 v0 = __ldg(&h[(size_t)s0 * C2 + lane]);
        float2 v1 = __ldg(&h[(size_t)s1 * C2 + lane]);
        ax += v0.x * n0 + v1.x * n1;
        ay += v0.y * n0 + v1.y * n1;
    }
    if (j < end) {
        int   s0 = __ldg(&g_esrc[j]);
        float n0 = __ldg(&g_enorm[j]);
        float2 v0 = __ldg(&h[(size_t)s0 * C2 + lane]);
        ax += v0.x * n0;
        ay += v0.y * n0;
    }

    float di = g_dinv[node];
    float d2 = di * di;
    float2 hv = h[(size_t)node * C2 + lane];
    float2 bv = ((const float2*)b)[lane];
    float2 o;
    o.x = ax + hv.x * d2 + bv.x;
    o.y = ay + hv.y * d2 + bv.y;
    out[(size_t)node * C2 + lane] = o;
}

// -------- CSR gather layer 2 (F=32) + relu + classifier + log_softmax --------
__global__ void k_gather32f(const float* __restrict__ b, const float* __restrict__ Wc,
                            const float* __restrict__ bc, float* __restrict__ outp,
                            int N) {
    constexpr int F = H2D;
    __shared__ float WcSm[H2D * NCLS];
    __shared__ float bcSm[NCLS];
    int tid = threadIdx.x;
    for (int i = tid; i < H2D * NCLS; i += blockDim.x) WcSm[i] = Wc[i];
    if (tid < NCLS) bcSm[tid] = bc[tid];
    __syncthreads();

    int node = blockIdx.x * (blockDim.x >> 5) + (tid >> 5);
    int lane = tid & 31;
    if (node >= N) return;

    const float* h = g_h2;
    int beg = g_off[node];
    int end = g_off[node + 1];

    float acc = 0.0f;
    int j = beg;
    for (; j + 1 < end; j += 2) {
        int   s0 = __ldg(&g_esrc[j]);
        int   s1 = __ldg(&g_esrc[j + 1]);
        float n0 = __ldg(&g_enorm[j]);
        float n1 = __ldg(&g_enorm[j + 1]);
        acc += __ldg(&h[(size_t)s0 * F + lane]) * n0;
        acc += __ldg(&h[(size_t)s1 * F + lane]) * n1;
    }
    if (j < end) {
        int   s0 = __ldg(&g_esrc[j]);
        float n0 = __ldg(&g_enorm[j]);
        acc += __ldg(&h[(size_t)s0 * F + lane]) * n0;
    }

    float di = g_dinv[node];
    float x = acc + h[(size_t)node * F + lane] * di * di + b[lane];
    x = fmaxf(x, 0.0f);

    float p[NCLS];
#pragma unroll
    for (int c = 0; c < NCLS; c++) p[c] = x * WcSm[lane * NCLS + c];
#pragma unroll
    for (int s = 16; s > 0; s >>= 1)
#pragma unroll
        for (int c = 0; c < NCLS; c++)
            p[c] += __shfl_xor_sync(0xffffffffu, p[c], s);

    float lg[NCLS];
#pragma unroll
    for (int c = 0; c < NCLS; c++) lg[c] = p[c] + bcSm[c];
    float mx = lg[0];
#pragma unroll
    for (int c = 1; c < NCLS; c++) mx = fmaxf(mx, lg[c]);
    float sum = 0.0f;
#pragma unroll
    for (int c = 0; c < NCLS; c++) sum += __expf(lg[c] - mx);
    float lse = mx + logf(sum);

    if (lane < NCLS) outp[(size_t)node * NCLS + lane] = lg[lane] - lse;
}

// ---------------- launch (kernel launches ONLY; graph-capture clean) ---------
extern "C" void kernel_launch(void* const* d_in, const int* in_sizes, int n_in,
                              void* d_out, int out_size) {
    const float* feat = (const float*)d_in[0];
    const int*   ei   = (const int*)d_in[1];    // int32 (JAX x64 disabled)
    const float* W1   = (const float*)d_in[2];
    const float* b1   = (const float*)d_in[3];
    const float* W2   = (const float*)d_in[4];
    const float* b2   = (const float*)d_in[5];
    const float* Wc   = (const float*)d_in[6];
    const float* bc   = (const float*)d_in[7];

    int N = in_sizes[0] / FIN;
    int E = in_sizes[1] / 2;

    const int T = 256;
    int nb = (N + SCAN_B - 1) / SCAN_B;

    // CSR build (new gemm1 at slot 4 so ncu profiles it next round)
    k_zero<<<(N + T - 1) / T, T>>>(N);
    k_count<<<(E + T - 1) / T, T>>>(ei, E);
    k_scan1<<<nb, SCAN_B>>>(N);
    k_gemm2x<FIN, H1D, false, 1><<<(N + 127) / 128, 256>>>(feat, W1, N);  // #4
    k_scan2<<<1, 256>>>(nb);
    k_scan3<<<(N + T - 1) / T, T>>>(N, E);
    k_dinv<<<(N + T - 1) / T, T>>>(N);
    k_fill<<<(E + T - 1) / T, T>>>(ei, E);

    // layer 1 aggregation
    k_gather64<<<(N + 7) / 8, 256>>>(b1, N);

    // layer 2 + fused classifier/log_softmax
    k_gemm2x<H1D, H2D, true, 2><<<(N + 255) / 256, 256>>>(nullptr, W2, N);
    k_gather32f<<<(N + 7) / 8, 256>>>(b2, Wc, bc, (float*)d_out, N);
}

// round 12
// speedup vs baseline: 1.2040x; 1.0660x over previous
#include <cuda_runtime.h>
#include <math.h>
#include <stdint.h>

#define MAX_E 3200000
#define MAX_N 100000
#define FIN 128
#define H1D 64
#define H2D 32
#define NCLS 10
#define SCAN_B 512
#define MAX_BLKS ((MAX_N + SCAN_B) / SCAN_B + 2)

// ---------------- scratch (device globals; referenced directly, no host APIs)
__device__ __align__(16) int   g_indeg[MAX_N];
__device__ __align__(16) int   g_off[MAX_N + 1];
__device__ __align__(16) int   g_pos[MAX_N];
__device__ __align__(16) int   g_part[MAX_N];
__device__ __align__(16) int   g_bsum[MAX_BLKS];
__device__ __align__(16) float g_dinv[MAX_N];
__device__ __align__(16) int   g_esrc[MAX_E];
__device__ __align__(16) float g_enorm[MAX_E];
__device__ __align__(16) float g_h1[MAX_N * H1D];
__device__ __align__(16) float g_a1[MAX_N * H1D];
__device__ __align__(16) float g_h2[MAX_N * H2D];

// ---------------- f32x2 helpers ----------------------------------------------
__device__ __forceinline__ uint64_t pk2(float lo, float hi) {
    uint64_t r; asm("mov.b64 %0, {%1,%2};" : "=l"(r) : "f"(lo), "f"(hi)); return r;
}
__device__ __forceinline__ void upk2(uint64_t v, float& lo, float& hi) {
    asm("mov.b64 {%0,%1}, %2;" : "=f"(lo), "=f"(hi) : "l"(v));
}
__device__ __forceinline__ void fma2(uint64_t& d, uint64_t a, uint64_t b) {
    asm("fma.rn.f32x2 %0, %1, %2, %0;" : "+l"(d) : "l"(a), "l"(b));
}

// ---------------- CSR build ---------------------------------------------------
__global__ void k_zero(int N) {
    int i = blockIdx.x * blockDim.x + threadIdx.x;
    if (i < N) g_indeg[i] = 0;
}

__global__ void k_count(const int* __restrict__ ei, int E) {
    int e = blockIdx.x * blockDim.x + threadIdx.x;
    if (e >= E) return;
    atomicAdd(&g_indeg[ei[e + E]], 1);
}

__global__ void k_scan1(int N) {
    __shared__ int sm[SCAN_B];
    int gid = blockIdx.x * SCAN_B + threadIdx.x;
    int v = (gid < N) ? g_indeg[gid] : 0;
    sm[threadIdx.x] = v;
    __syncthreads();
#pragma unroll
    for (int s = 1; s < SCAN_B; s <<= 1) {
        int t = (threadIdx.x >= (unsigned)s) ? sm[threadIdx.x - s] : 0;
        __syncthreads();
        sm[threadIdx.x] += t;
        __syncthreads();
    }
    if (gid < N) g_part[gid] = sm[threadIdx.x] - v;
    if (threadIdx.x == SCAN_B - 1) g_bsum[blockIdx.x] = sm[threadIdx.x];
}

__global__ void k_scan2(int nb) {
    __shared__ int sm[256];
    int t = threadIdx.x;
    int v = (t < nb) ? g_bsum[t] : 0;
    sm[t] = v;
    __syncthreads();
#pragma unroll
    for (int s = 1; s < 256; s <<= 1) {
        int u = (t >= (unsigned)s) ? sm[t - s] : 0;
        __syncthreads();
        sm[t] += u;
        __syncthreads();
    }
    if (t < nb) g_bsum[t] = sm[t] - v;
}

__global__ void k_scan3(int N, int E) {
    int gid = blockIdx.x * blockDim.x + threadIdx.x;
    if (gid < N) {
        int o = g_part[gid] + g_bsum[gid / SCAN_B];
        g_off[gid] = o;
        g_pos[gid] = o;
    }
    if (gid == 0) g_off[N] = E;
}

__global__ void k_dinv(int N) {
    int i = blockIdx.x * blockDim.x + threadIdx.x;
    if (i < N) g_dinv[i] = rsqrtf((float)g_indeg[i] + 1.0f);
}

__global__ void k_fill(const int* __restrict__ ei, int E) {
    int e = blockIdx.x * blockDim.x + threadIdx.x;
    if (e >= E) return;
    int s = ei[e];
    int d = ei[e + E];
    int p = atomicAdd(&g_pos[d], 1);
    g_esrc[p]  = s;
    g_enorm[p] = g_dinv[s] * g_dinv[d];
}

// ---------------- f32x2 GEMM: out = (relu?)X @ W ------------------------------
// 256 threads; thread tile RT rows x 8 cols (4 f32x2 accs per row).
// Xs transposed [k][row] (LDS.128 = 4 rows), Ws [k][col] (native f32x2 pairs).
template <int KDIM, int ODIM, bool RELU_IN, int LAYER, int RT>
__global__ void __launch_bounds__(256, 2)
k_gemm2x(const float* __restrict__ Xparam, const float* __restrict__ Wg, int N) {
    constexpr int KC   = 32;          // k-chunk
    constexpr int COLG = ODIM / 8;    // col groups
    constexpr int ROWG = 256 / COLG;  // row groups
    constexpr int TM   = ROWG * RT;   // rows per block
    constexpr int XP   = TM + 4;      // padded row stride (keeps 16B align)

    const float* X  = (LAYER == 1) ? Xparam : g_a1;
    float*      out = (LAYER == 1) ? g_h1   : g_h2;

    __shared__ float Xs[KC][XP];
    __shared__ float Ws[KC][ODIM];

    int tid  = threadIdx.x;
    int row0 = blockIdx.x * TM;
    int tx = tid % COLG, ty = tid / COLG;
    int c0 = tx * 8, r0 = ty * RT;

    uint64_t acc[RT][4];
#pragma unroll
    for (int r = 0; r < RT; r++)
#pragma unroll
        for (int p = 0; p < 4; p++) acc[r][p] = 0ULL;

    for (int k0 = 0; k0 < KDIM; k0 += KC) {
        __syncthreads();
        // W chunk: contiguous KC*ODIM floats
        {
            const float4* src = (const float4*)(Wg + (size_t)k0 * ODIM);
            float4* dst = (float4*)&Ws[0][0];
            for (int i = tid; i < KC * ODIM / 4; i += 256) dst[i] = src[i];
        }
        // X chunk, transposed into Xs[k][row]
        for (int i = tid; i < TM * (KC / 4); i += 256) {
            int r = i / (KC / 4);
            int q = i - r * (KC / 4);
            int gr = row0 + r;
            float4 v = make_float4(0.f, 0.f, 0.f, 0.f);
            if (gr < N) v = *(const float4*)(X + (size_t)gr * KDIM + k0 + q * 4);
            if (RELU_IN) {
                v.x = fmaxf(v.x, 0.f); v.y = fmaxf(v.y, 0.f);
                v.z = fmaxf(v.z, 0.f); v.w = fmaxf(v.w, 0.f);
            }
            Xs[q * 4 + 0][r] = v.x;
            Xs[q * 4 + 1][r] = v.y;
            Xs[q * 4 + 2][r] = v.z;
            Xs[q * 4 + 3][r] = v.w;
        }
        __syncthreads();

#pragma unroll 4
        for (int k = 0; k < KC; k++) {
            ulonglong2 wa = *(const ulonglong2*)&Ws[k][c0];
            ulonglong2 wb = *(const ulonglong2*)&Ws[k][c0 + 4];
            uint64_t wp[4] = {wa.x, wa.y, wb.x, wb.y};
#pragma unroll
            for (int rr = 0; rr < RT / 4; rr++) {
                float4 xv = *(const float4*)&Xs[k][r0 + rr * 4];
                uint64_t xb[4] = {pk2(xv.x, xv.x), pk2(xv.y, xv.y),
                                  pk2(xv.z, xv.z), pk2(xv.w, xv.w)};
#pragma unroll
                for (int r = 0; r < 4; r++)
#pragma unroll
                    for (int p = 0; p < 4; p++)
                        fma2(acc[rr * 4 + r][p], xb[r], wp[p]);
            }
        }
    }

#pragma unroll
    for (int r = 0; r < RT; r++) {
        int gr = row0 + r0 + r;
        if (gr >= N) continue;
        float4 o0, o1;
        upk2(acc[r][0], o0.x, o0.y); upk2(acc[r][1], o0.z, o0.w);
        upk2(acc[r][2], o1.x, o1.y); upk2(acc[r][3], o1.z, o1.w);
        float4* dst = (float4*)(out + (size_t)gr * ODIM + c0);
        dst[0] = o0;
        dst[1] = o1;
    }
}

// -------- CSR gather layer 1 (F=64): float2 per lane (R9-proven) -------------
__global__ void k_gather64(const float* __restrict__ b, int N) {
    const float2* h = (const float2*)g_h1;
    float2*     out = (float2*)g_a1;
    constexpr int C2 = H1D / 2;

    int node = blockIdx.x * (blockDim.x >> 5) + (threadIdx.x >> 5);
    int lane = threadIdx.x & 31;
    if (node >= N) return;

    int beg = g_off[node];
    int end = g_off[node + 1];

    float ax = 0.0f, ay = 0.0f;
    int j = beg;
    for (; j + 1 < end; j += 2) {
        int   s0 = __ldg(&g_esrc[j]);
        int   s1 = __ldg(&g_esrc[j + 1]);
        float n0 = __ldg(&g_enorm[j]);
        float n1 = __ldg(&g_enorm[j + 1]);
        float2 v0 = __ldg(&h[(size_t)s0 * C2 + lane]);
        float2 v1 = __ldg(&h[(size_t)s1 * C2 + lane]);
        ax += v0.x * n0 + v1.x * n1;
        ay += v0.y * n0 + v1.y * n1;
    }
    if (j < end) {
        int   s0 = __ldg(&g_esrc[j]);
        float n0 = __ldg(&g_enorm[j]);
        float2 v0 = __ldg(&h[(size_t)s0 * C2 + lane]);
        ax += v0.x * n0;
        ay += v0.y * n0;
    }

    float di = g_dinv[node];
    float d2 = di * di;
    float2 hv = h[(size_t)node * C2 + lane];
    float2 bv = ((const float2*)b)[lane];
    float2 o;
    o.x = ax + hv.x * d2 + bv.x;
    o.y = ay + hv.y * d2 + bv.y;
    out[(size_t)node * C2 + lane] = o;
}

// -------- CSR gather layer 2 (F=32) + relu + classifier + log_softmax --------
__global__ void k_gather32f(const float* __restrict__ b, const float* __restrict__ Wc,
                            const float* __restrict__ bc, float* __restrict__ outp,
                            int N) {
    constexpr int F = H2D;
    __shared__ float WcSm[H2D * NCLS];
    __shared__ float bcSm[NCLS];
    int tid = threadIdx.x;
    for (int i = tid; i < H2D * NCLS; i += blockDim.x) WcSm[i] = Wc[i];
    if (tid < NCLS) bcSm[tid] = bc[tid];
    __syncthreads();

    int node = blockIdx.x * (blockDim.x >> 5) + (tid >> 5);
    int lane = tid & 31;
    if (node >= N) return;

    const float* h = g_h2;
    int beg = g_off[node];
    int end = g_off[node + 1];

    float acc = 0.0f;
    int j = beg;
    for (; j + 1 < end; j += 2) {
        int   s0 = __ldg(&g_esrc[j]);
        int   s1 = __ldg(&g_esrc[j + 1]);
        float n0 = __ldg(&g_enorm[j]);
        float n1 = __ldg(&g_enorm[j + 1]);
        acc += __ldg(&h[(size_t)s0 * F + lane]) * n0;
        acc += __ldg(&h[(size_t)s1 * F + lane]) * n1;
    }
    if (j < end) {
        int   s0 = __ldg(&g_esrc[j]);
        float n0 = __ldg(&g_enorm[j]);
        acc += __ldg(&h[(size_t)s0 * F + lane]) * n0;
    }

    float di = g_dinv[node];
    float x = acc + h[(size_t)node * F + lane] * di * di + b[lane];
    x = fmaxf(x, 0.0f);

    float p[NCLS];
#pragma unroll
    for (int c = 0; c < NCLS; c++) p[c] = x * WcSm[lane * NCLS + c];
#pragma unroll
    for (int s = 16; s > 0; s >>= 1)
#pragma unroll
        for (int c = 0; c < NCLS; c++)
            p[c] += __shfl_xor_sync(0xffffffffu, p[c], s);

    float lg[NCLS];
#pragma unroll
    for (int c = 0; c < NCLS; c++) lg[c] = p[c] + bcSm[c];
    float mx = lg[0];
#pragma unroll
    for (int c = 1; c < NCLS; c++) mx = fmaxf(mx, lg[c]);
    float sum = 0.0f;
#pragma unroll
    for (int c = 0; c < NCLS; c++) sum += __expf(lg[c] - mx);
    float lse = mx + logf(sum);

    if (lane < NCLS) outp[(size_t)node * NCLS + lane] = lg[lane] - lse;
}

// ---------------- launch (kernel launches ONLY; graph-capture clean) ---------
extern "C" void kernel_launch(void* const* d_in, const int* in_sizes, int n_in,
                              void* d_out, int out_size) {
    const float* feat = (const float*)d_in[0];
    const int*   ei   = (const int*)d_in[1];    // int32 (JAX x64 disabled)
    const float* W1   = (const float*)d_in[2];
    const float* b1   = (const float*)d_in[3];
    const float* W2   = (const float*)d_in[4];
    const float* b2   = (const float*)d_in[5];
    const float* Wc   = (const float*)d_in[6];
    const float* bc   = (const float*)d_in[7];

    int N = in_sizes[0] / FIN;
    int E = in_sizes[1] / 2;

    const int T = 256;
    int nb = (N + SCAN_B - 1) / SCAN_B;

    // CSR build (gemm1 at slot 4 so ncu profiles it)
    k_zero<<<(N + T - 1) / T, T>>>(N);
    k_count<<<(E + T - 1) / T, T>>>(ei, E);
    k_scan1<<<nb, SCAN_B>>>(N);
    k_gemm2x<FIN, H1D, false, 1, 8><<<(N + 255) / 256, 256>>>(feat, W1, N);  // #4
    k_scan2<<<1, 256>>>(nb);
    k_scan3<<<(N + T - 1) / T, T>>>(N, E);
    k_dinv<<<(N + T - 1) / T, T>>>(N);
    k_fill<<<(E + T - 1) / T, T>>>(ei, E);

    // layer 1 aggregation
    k_gather64<<<(N + 7) / 8, 256>>>(b1, N);

    // layer 2 + fused classifier/log_softmax
    k_gemm2x<H1D, H2D, true, 2, 4><<<(N + 255) / 256, 256>>>(nullptr, W2, N);
    k_gather32f<<<(N + 7) / 8, 256>>>(b2, Wc, bc, (float*)d_out, N);
}

// round 13
// speedup vs baseline: 1.2147x; 1.0090x over previous
#include <cuda_runtime.h>
#include <cuda_fp16.h>
#include <math.h>
#include <stdint.h>

#define MAX_E 3200000
#define MAX_N 100000
#define FIN 128
#define H1D 64
#define H2D 32
#define NCLS 10
#define SCAN_B 512
#define MAX_BLKS ((MAX_N + SCAN_B) / SCAN_B + 2)

// ---------------- scratch (device globals; referenced directly, no host APIs)
__device__ __align__(16) int    g_indeg[MAX_N];
__device__ __align__(16) int    g_off[MAX_N + 1];
__device__ __align__(16) int    g_pos[MAX_N];
__device__ __align__(16) int    g_part[MAX_N];
__device__ __align__(16) int    g_bsum[MAX_BLKS];
__device__ __align__(16) float  g_dinv[MAX_N];
__device__ __align__(16) int    g_esrc[MAX_E];
__device__ __align__(16) float  g_enorm[MAX_E];
__device__ __align__(16) __half g_h1[MAX_N * H1D];   // fp16 storage for gather
__device__ __align__(16) float  g_a1[MAX_N * H1D];
__device__ __align__(16) __half g_h2[MAX_N * H2D];   // fp16 storage for gather

// ---------------- f32x2 helpers ----------------------------------------------
__device__ __forceinline__ uint64_t pk2(float lo, float hi) {
    uint64_t r; asm("mov.b64 %0, {%1,%2};" : "=l"(r) : "f"(lo), "f"(hi)); return r;
}
__device__ __forceinline__ void upk2(uint64_t v, float& lo, float& hi) {
    asm("mov.b64 {%0,%1}, %2;" : "=f"(lo), "=f"(hi) : "l"(v));
}
__device__ __forceinline__ void fma2(uint64_t& d, uint64_t a, uint64_t b) {
    asm("fma.rn.f32x2 %0, %1, %2, %0;" : "+l"(d) : "l"(a), "l"(b));
}

struct alignas(16) H8 { __half2 a, b, c, d; };  // 8 halves = 16B store

// ---------------- CSR build ---------------------------------------------------
__global__ void k_zero(int N) {
    int i = blockIdx.x * blockDim.x + threadIdx.x;
    if (i < N) g_indeg[i] = 0;
}

__global__ void k_count(const int* __restrict__ ei, int E) {
    int e = blockIdx.x * blockDim.x + threadIdx.x;
    if (e >= E) return;
    atomicAdd(&g_indeg[ei[e + E]], 1);
}

__global__ void k_scan1(int N) {
    __shared__ int sm[SCAN_B];
    int gid = blockIdx.x * SCAN_B + threadIdx.x;
    int v = (gid < N) ? g_indeg[gid] : 0;
    sm[threadIdx.x] = v;
    __syncthreads();
#pragma unroll
    for (int s = 1; s < SCAN_B; s <<= 1) {
        int t = (threadIdx.x >= (unsigned)s) ? sm[threadIdx.x - s] : 0;
        __syncthreads();
        sm[threadIdx.x] += t;
        __syncthreads();
    }
    if (gid < N) g_part[gid] = sm[threadIdx.x] - v;
    if (threadIdx.x == SCAN_B - 1) g_bsum[blockIdx.x] = sm[threadIdx.x];
}

__global__ void k_scan2(int nb) {
    __shared__ int sm[256];
    int t = threadIdx.x;
    int v = (t < nb) ? g_bsum[t] : 0;
    sm[t] = v;
    __syncthreads();
#pragma unroll
    for (int s = 1; s < 256; s <<= 1) {
        int u = (t >= (unsigned)s) ? sm[t - s] : 0;
        __syncthreads();
        sm[t] += u;
        __syncthreads();
    }
    if (t < nb) g_bsum[t] = sm[t] - v;
}

__global__ void k_scan3(int N, int E) {
    int gid = blockIdx.x * blockDim.x + threadIdx.x;
    if (gid < N) {
        int o = g_part[gid] + g_bsum[gid / SCAN_B];
        g_off[gid] = o;
        g_pos[gid] = o;
    }
    if (gid == 0) g_off[N] = E;
}

__global__ void k_dinv(int N) {
    int i = blockIdx.x * blockDim.x + threadIdx.x;
    if (i < N) g_dinv[i] = rsqrtf((float)g_indeg[i] + 1.0f);
}

__global__ void k_fill(const int* __restrict__ ei, int E) {
    int e = blockIdx.x * blockDim.x + threadIdx.x;
    if (e >= E) return;
    int s = ei[e];
    int d = ei[e + E];
    int p = atomicAdd(&g_pos[d], 1);
    g_esrc[p]  = s;
    g_enorm[p] = g_dinv[s] * g_dinv[d];
}

// ---------------- f32x2 GEMM: out(fp16) = (relu?)X @ W ------------------------
template <int KDIM, int ODIM, bool RELU_IN, int LAYER, int RT>
__global__ void __launch_bounds__(256, 2)
k_gemm2x(const float* __restrict__ Xparam, const float* __restrict__ Wg, int N) {
    constexpr int KC   = 32;
    constexpr int COLG = ODIM / 8;
    constexpr int ROWG = 256 / COLG;
    constexpr int TM   = ROWG * RT;
    constexpr int XP   = TM + 4;

    const float* X  = (LAYER == 1) ? Xparam : g_a1;
    __half*     out = (LAYER == 1) ? g_h1   : g_h2;

    __shared__ float Xs[KC][XP];
    __shared__ float Ws[KC][ODIM];

    int tid  = threadIdx.x;
    int row0 = blockIdx.x * TM;
    int tx = tid % COLG, ty = tid / COLG;
    int c0 = tx * 8, r0 = ty * RT;

    uint64_t acc[RT][4];
#pragma unroll
    for (int r = 0; r < RT; r++)
#pragma unroll
        for (int p = 0; p < 4; p++) acc[r][p] = 0ULL;

    for (int k0 = 0; k0 < KDIM; k0 += KC) {
        __syncthreads();
        {
            const float4* src = (const float4*)(Wg + (size_t)k0 * ODIM);
            float4* dst = (float4*)&Ws[0][0];
            for (int i = tid; i < KC * ODIM / 4; i += 256) dst[i] = src[i];
        }
        for (int i = tid; i < TM * (KC / 4); i += 256) {
            int r = i / (KC / 4);
            int q = i - r * (KC / 4);
            int gr = row0 + r;
            float4 v = make_float4(0.f, 0.f, 0.f, 0.f);
            if (gr < N) v = *(const float4*)(X + (size_t)gr * KDIM + k0 + q * 4);
            if (RELU_IN) {
                v.x = fmaxf(v.x, 0.f); v.y = fmaxf(v.y, 0.f);
                v.z = fmaxf(v.z, 0.f); v.w = fmaxf(v.w, 0.f);
            }
            Xs[q * 4 + 0][r] = v.x;
            Xs[q * 4 + 1][r] = v.y;
            Xs[q * 4 + 2][r] = v.z;
            Xs[q * 4 + 3][r] = v.w;
        }
        __syncthreads();

#pragma unroll 4
        for (int k = 0; k < KC; k++) {
            ulonglong2 wa = *(const ulonglong2*)&Ws[k][c0];
            ulonglong2 wb = *(const ulonglong2*)&Ws[k][c0 + 4];
            uint64_t wp[4] = {wa.x, wa.y, wb.x, wb.y};
#pragma unroll
            for (int rr = 0; rr < RT / 4; rr++) {
                float4 xv = *(const float4*)&Xs[k][r0 + rr * 4];
                uint64_t xb[4] = {pk2(xv.x, xv.x), pk2(xv.y, xv.y),
                                  pk2(xv.z, xv.z), pk2(xv.w, xv.w)};
#pragma unroll
                for (int r = 0; r < 4; r++)
#pragma unroll
                    for (int p = 0; p < 4; p++)
                        fma2(acc[rr * 4 + r][p], xb[r], wp[p]);
            }
        }
    }

#pragma unroll
    for (int r = 0; r < RT; r++) {
        int gr = row0 + r0 + r;
        if (gr >= N) continue;
        float4 o0, o1;
        upk2(acc[r][0], o0.x, o0.y); upk2(acc[r][1], o0.z, o0.w);
        upk2(acc[r][2], o1.x, o1.y); upk2(acc[r][3], o1.z, o1.w);
        H8 hpk;
        hpk.a = __floats2half2_rn(o0.x, o0.y);
        hpk.b = __floats2half2_rn(o0.z, o0.w);
        hpk.c = __floats2half2_rn(o1.x, o1.y);
        hpk.d = __floats2half2_rn(o1.z, o1.w);
        *(H8*)(out + (size_t)gr * ODIM + c0) = hpk;
    }
}

// -------- CSR gather layer 1 (F=64): half2 per lane --------------------------
// a1[i] = sum_j h1[src_j]*norm_j + h1[i]*dinv[i]^2 + b1   (h1 fp16, acc fp32)
__global__ void k_gather64(const float* __restrict__ b, int N) {
    const __half2* h = (const __half2*)g_h1;
    float2*      out = (float2*)g_a1;
    constexpr int C2 = H1D / 2;   // 32 half2 per row: one per lane

    int node = blockIdx.x * (blockDim.x >> 5) + (threadIdx.x >> 5);
    int lane = threadIdx.x & 31;
    if (node >= N) return;

    int beg = g_off[node];
    int end = g_off[node + 1];

    float ax = 0.0f, ay = 0.0f;
    int j = beg;
    for (; j + 1 < end; j += 2) {
        int   s0 = __ldg(&g_esrc[j]);
        int   s1 = __ldg(&g_esrc[j + 1]);
        float n0 = __ldg(&g_enorm[j]);
        float n1 = __ldg(&g_enorm[j + 1]);
        float2 v0 = __half22float2(__ldg(&h[(size_t)s0 * C2 + lane]));
        float2 v1 = __half22float2(__ldg(&h[(size_t)s1 * C2 + lane]));
        ax += v0.x * n0 + v1.x * n1;
        ay += v0.y * n0 + v1.y * n1;
    }
    if (j < end) {
        int   s0 = __ldg(&g_esrc[j]);
        float n0 = __ldg(&g_enorm[j]);
        float2 v0 = __half22float2(__ldg(&h[(size_t)s0 * C2 + lane]));
        ax += v0.x * n0;
        ay += v0.y * n0;
    }

    float di = g_dinv[node];
    float d2 = di * di;
    float2 hv = __half22float2(h[(size_t)node * C2 + lane]);
    float2 bv = ((const float2*)b)[lane];
    float2 o;
    o.x = ax + hv.x * d2 + bv.x;
    o.y = ay + hv.y * d2 + bv.y;
    out[(size_t)node * C2 + lane] = o;
}

// -------- CSR gather layer 2 (F=32, fp16) + relu + classifier + log_softmax --
__global__ void k_gather32f(const float* __restrict__ b, const float* __restrict__ Wc,
                            const float* __restrict__ bc, float* __restrict__ outp,
                            int N) {
    constexpr int F = H2D;
    __shared__ float WcSm[H2D * NCLS];
    __shared__ float bcSm[NCLS];
    int tid = threadIdx.x;
    for (int i = tid; i < H2D * NCLS; i += blockDim.x) WcSm[i] = Wc[i];
    if (tid < NCLS) bcSm[tid] = bc[tid];
    __syncthreads();

    int node = blockIdx.x * (blockDim.x >> 5) + (tid >> 5);
    int lane = tid & 31;
    if (node >= N) return;

    const __half* h = g_h2;
    int beg = g_off[node];
    int end = g_off[node + 1];

    float acc = 0.0f;
    int j = beg;
    for (; j + 1 < end; j += 2) {
        int   s0 = __ldg(&g_esrc[j]);
        int   s1 = __ldg(&g_esrc[j + 1]);
        float n0 = __ldg(&g_enorm[j]);
        float n1 = __ldg(&g_enorm[j + 1]);
        acc += __half2float(__ldg(&h[(size_t)s0 * F + lane])) * n0;
        acc += __half2float(__ldg(&h[(size_t)s1 * F + lane])) * n1;
    }
    if (j < end) {
        int   s0 = __ldg(&g_esrc[j]);
        float n0 = __ldg(&g_enorm[j]);
        acc += __half2float(__ldg(&h[(size_t)s0 * F + lane])) * n0;
    }

    float di = g_dinv[node];
    float x = acc + __half2float(h[(size_t)node * F + lane]) * di * di + b[lane];
    x = fmaxf(x, 0.0f);

    float p[NCLS];
#pragma unroll
    for (int c = 0; c < NCLS; c++) p[c] = x * WcSm[lane * NCLS + c];
#pragma unroll
    for (int s = 16; s > 0; s >>= 1)
#pragma unroll
        for (int c = 0; c < NCLS; c++)
            p[c] += __shfl_xor_sync(0xffffffffu, p[c], s);

    float lg[NCLS];
#pragma unroll
    for (int c = 0; c < NCLS; c++) lg[c] = p[c] + bcSm[c];
    float mx = lg[0];
#pragma unroll
    for (int c = 1; c < NCLS; c++) mx = fmaxf(mx, lg[c]);
    float sum = 0.0f;
#pragma unroll
    for (int c = 0; c < NCLS; c++) sum += __expf(lg[c] - mx);
    float lse = mx + logf(sum);

    if (lane < NCLS) outp[(size_t)node * NCLS + lane] = lg[lane] - lse;
}

// ---------------- launch (kernel launches ONLY; graph-capture clean) ---------
extern "C" void kernel_launch(void* const* d_in, const int* in_sizes, int n_in,
                              void* d_out, int out_size) {
    const float* feat = (const float*)d_in[0];
    const int*   ei   = (const int*)d_in[1];    // int32 (JAX x64 disabled)
    const float* W1   = (const float*)d_in[2];
    const float* b1   = (const float*)d_in[3];
    const float* W2   = (const float*)d_in[4];
    const float* b2   = (const float*)d_in[5];
    const float* Wc   = (const float*)d_in[6];
    const float* bc   = (const float*)d_in[7];

    int N = in_sizes[0] / FIN;
    int E = in_sizes[1] / 2;

    const int T = 256;
    int nb = (N + SCAN_B - 1) / SCAN_B;

    // CSR build (gemm1 at slot 4 so ncu profiles it)
    k_zero<<<(N + T - 1) / T, T>>>(N);
    k_count<<<(E + T - 1) / T, T>>>(ei, E);
    k_scan1<<<nb, SCAN_B>>>(N);
    k_gemm2x<FIN, H1D, false, 1, 8><<<(N + 255) / 256, 256>>>(feat, W1, N);  // #4
    k_scan2<<<1, 256>>>(nb);
    k_scan3<<<(N + T - 1) / T, T>>>(N, E);
    k_dinv<<<(N + T - 1) / T, T>>>(N);
    k_fill<<<(E + T - 1) / T, T>>>(ei, E);

    // layer 1 aggregation
    k_gather64<<<(N + 7) / 8, 256>>>(b1, N);

    // layer 2 + fused classifier/log_softmax
    k_gemm2x<H1D, H2D, true, 2, 4><<<(N + 255) / 256, 256>>>(nullptr, W2, N);
    k_gather32f<<<(N + 7) / 8, 256>>>(b2, Wc, bc, (float*)d_out, N);
}

// round 14
// speedup vs baseline: 1.2300x; 1.0125x over previous
#include <cuda_runtime.h>
#include <cuda_fp16.h>
#include <math.h>
#include <stdint.h>

#define MAX_E 3200000
#define MAX_N 100000
#define FIN 128
#define H1D 64
#define H2D 32
#define NCLS 10
#define SCAN_B 512
#define MAX_BLKS ((MAX_N + SCAN_B) / SCAN_B + 2)

// ---------------- scratch (device globals; referenced directly, no host APIs)
__device__ __align__(16) int    g_indeg[MAX_N];
__device__ __align__(16) int    g_off[MAX_N + 1];
__device__ __align__(16) int    g_pos[MAX_N];
__device__ __align__(16) int    g_part[MAX_N];
__device__ __align__(16) int    g_bsum[MAX_BLKS];
__device__ __align__(16) float  g_dinv[MAX_N];
__device__ __align__(16) int2   g_edge[MAX_E];       // (src, norm bits)
__device__ __align__(16) __half g_h1[MAX_N * H1D];   // fp16 storage for gather
__device__ __align__(16) float  g_a1[MAX_N * H1D];
__device__ __align__(16) __half g_h2[MAX_N * H2D];   // fp16 storage for gather

// ---------------- f32x2 helpers ----------------------------------------------
__device__ __forceinline__ uint64_t pk2(float lo, float hi) {
    uint64_t r; asm("mov.b64 %0, {%1,%2};" : "=l"(r) : "f"(lo), "f"(hi)); return r;
}
__device__ __forceinline__ void upk2(uint64_t v, float& lo, float& hi) {
    asm("mov.b64 {%0,%1}, %2;" : "=f"(lo), "=f"(hi) : "l"(v));
}
__device__ __forceinline__ void fma2(uint64_t& d, uint64_t a, uint64_t b) {
    asm("fma.rn.f32x2 %0, %1, %2, %0;" : "+l"(d) : "l"(a), "l"(b));
}

struct alignas(16) H8 { __half2 a, b, c, d; };  // 8 halves = 16B store

// ---------------- CSR build ---------------------------------------------------
__global__ void k_zero(int N) {
    int i = blockIdx.x * blockDim.x + threadIdx.x;
    if (i < N) g_indeg[i] = 0;
}

__global__ void k_count(const int* __restrict__ ei, int E) {
    int e = blockIdx.x * blockDim.x + threadIdx.x;
    if (e >= E) return;
    atomicAdd(&g_indeg[ei[e + E]], 1);
}

__global__ void k_scan1(int N) {
    __shared__ int sm[SCAN_B];
    int gid = blockIdx.x * SCAN_B + threadIdx.x;
    int v = (gid < N) ? g_indeg[gid] : 0;
    sm[threadIdx.x] = v;
    __syncthreads();
#pragma unroll
    for (int s = 1; s < SCAN_B; s <<= 1) {
        int t = (threadIdx.x >= (unsigned)s) ? sm[threadIdx.x - s] : 0;
        __syncthreads();
        sm[threadIdx.x] += t;
        __syncthreads();
    }
    if (gid < N) g_part[gid] = sm[threadIdx.x] - v;
    if (threadIdx.x == SCAN_B - 1) g_bsum[blockIdx.x] = sm[threadIdx.x];
}

__global__ void k_scan2(int nb) {
    __shared__ int sm[256];
    int t = threadIdx.x;
    int v = (t < nb) ? g_bsum[t] : 0;
    sm[t] = v;
    __syncthreads();
#pragma unroll
    for (int s = 1; s < 256; s <<= 1) {
        int u = (t >= (unsigned)s) ? sm[t - s] : 0;
        __syncthreads();
        sm[t] += u;
        __syncthreads();
    }
    if (t < nb) g_bsum[t] = sm[t] - v;
}

__global__ void k_scan3(int N, int E) {
    int gid = blockIdx.x * blockDim.x + threadIdx.x;
    if (gid < N) {
        int o = g_part[gid] + g_bsum[gid / SCAN_B];
        g_off[gid] = o;
        g_pos[gid] = o;
    }
    if (gid == 0) g_off[N] = E;
}

__global__ void k_dinv(int N) {
    int i = blockIdx.x * blockDim.x + threadIdx.x;
    if (i < N) g_dinv[i] = rsqrtf((float)g_indeg[i] + 1.0f);
}

__global__ void k_fill(const int* __restrict__ ei, int E) {
    int e = blockIdx.x * blockDim.x + threadIdx.x;
    if (e >= E) return;
    int s = ei[e];
    int d = ei[e + E];
    int p = atomicAdd(&g_pos[d], 1);
    g_edge[p] = make_int2(s, __float_as_int(g_dinv[s] * g_dinv[d]));
}

// ---------------- f32x2 GEMM: out(fp16) = (relu?)X @ W ------------------------
template <int KDIM, int ODIM, bool RELU_IN, int LAYER, int RT>
__global__ void __launch_bounds__(256, 2)
k_gemm2x(const float* __restrict__ Xparam, const float* __restrict__ Wg, int N) {
    constexpr int KC   = 32;
    constexpr int COLG = ODIM / 8;
    constexpr int ROWG = 256 / COLG;
    constexpr int TM   = ROWG * RT;
    constexpr int XP   = TM + 4;

    const float* X  = (LAYER == 1) ? Xparam : g_a1;
    __half*     out = (LAYER == 1) ? g_h1   : g_h2;

    __shared__ float Xs[KC][XP];
    __shared__ float Ws[KC][ODIM];

    int tid  = threadIdx.x;
    int row0 = blockIdx.x * TM;
    int tx = tid % COLG, ty = tid / COLG;
    int c0 = tx * 8, r0 = ty * RT;

    uint64_t acc[RT][4];
#pragma unroll
    for (int r = 0; r < RT; r++)
#pragma unroll
        for (int p = 0; p < 4; p++) acc[r][p] = 0ULL;

    for (int k0 = 0; k0 < KDIM; k0 += KC) {
        __syncthreads();
        {
            const float4* src = (const float4*)(Wg + (size_t)k0 * ODIM);
            float4* dst = (float4*)&Ws[0][0];
            for (int i = tid; i < KC * ODIM / 4; i += 256) dst[i] = src[i];
        }
        for (int i = tid; i < TM * (KC / 4); i += 256) {
            int r = i / (KC / 4);
            int q = i - r * (KC / 4);
            int gr = row0 + r;
            float4 v = make_float4(0.f, 0.f, 0.f, 0.f);
            if (gr < N) v = *(const float4*)(X + (size_t)gr * KDIM + k0 + q * 4);
            if (RELU_IN) {
                v.x = fmaxf(v.x, 0.f); v.y = fmaxf(v.y, 0.f);
                v.z = fmaxf(v.z, 0.f); v.w = fmaxf(v.w, 0.f);
            }
            Xs[q * 4 + 0][r] = v.x;
            Xs[q * 4 + 1][r] = v.y;
            Xs[q * 4 + 2][r] = v.z;
            Xs[q * 4 + 3][r] = v.w;
        }
        __syncthreads();

#pragma unroll 4
        for (int k = 0; k < KC; k++) {
            ulonglong2 wa = *(const ulonglong2*)&Ws[k][c0];
            ulonglong2 wb = *(const ulonglong2*)&Ws[k][c0 + 4];
            uint64_t wp[4] = {wa.x, wa.y, wb.x, wb.y};
#pragma unroll
            for (int rr = 0; rr < RT / 4; rr++) {
                float4 xv = *(const float4*)&Xs[k][r0 + rr * 4];
                uint64_t xb[4] = {pk2(xv.x, xv.x), pk2(xv.y, xv.y),
                                  pk2(xv.z, xv.z), pk2(xv.w, xv.w)};
#pragma unroll
                for (int r = 0; r < 4; r++)
#pragma unroll
                    for (int p = 0; p < 4; p++)
                        fma2(acc[rr * 4 + r][p], xb[r], wp[p]);
            }
        }
    }

#pragma unroll
    for (int r = 0; r < RT; r++) {
        int gr = row0 + r0 + r;
        if (gr >= N) continue;
        float4 o0, o1;
        upk2(acc[r][0], o0.x, o0.y); upk2(acc[r][1], o0.z, o0.w);
        upk2(acc[r][2], o1.x, o1.y); upk2(acc[r][3], o1.z, o1.w);
        H8 hpk;
        hpk.a = __floats2half2_rn(o0.x, o0.y);
        hpk.b = __floats2half2_rn(o0.z, o0.w);
        hpk.c = __floats2half2_rn(o1.x, o1.y);
        hpk.d = __floats2half2_rn(o1.z, o1.w);
        *(H8*)(out + (size_t)gr * ODIM + c0) = hpk;
    }
}

// -------- CSR gather layer 1 (F=64): warp-coop meta + half2 rows -------------
__global__ void k_gather64(const float* __restrict__ b, int N) {
    const __half2* h = (const __half2*)g_h1;
    float2*      out = (float2*)g_a1;
    constexpr int C2 = H1D / 2;

    int node = blockIdx.x * (blockDim.x >> 5) + (threadIdx.x >> 5);
    int lane = threadIdx.x & 31;
    if (node >= N) return;

    int beg = g_off[node];
    int end = g_off[node + 1];

    float ax = 0.0f, ay = 0.0f;
    int j = beg;
    // fast path: full 32-edge batches; 1 coalesced meta LDG per batch
    for (; j + 32 <= end; j += 32) {
        int2 m = __ldg(&g_edge[j + lane]);
#pragma unroll 8
        for (int k = 0; k < 32; k++) {
            int   s  = __shfl_sync(0xffffffffu, m.x, k);
            float nm = __int_as_float(__shfl_sync(0xffffffffu, m.y, k));
            float2 v = __half22float2(__ldg(&h[(size_t)s * C2 + lane]));
            ax += v.x * nm;
            ay += v.y * nm;
        }
    }
    // tail
    int rem = end - j;
    if (rem > 0) {
        int2 m = (lane < rem) ? __ldg(&g_edge[j + lane]) : make_int2(0, 0);
        for (int k = 0; k < rem; k++) {
            int   s  = __shfl_sync(0xffffffffu, m.x, k);
            float nm = __int_as_float(__shfl_sync(0xffffffffu, m.y, k));
            float2 v = __half22float2(__ldg(&h[(size_t)s * C2 + lane]));
            ax += v.x * nm;
            ay += v.y * nm;
        }
    }

    float di = g_dinv[node];
    float d2 = di * di;
    float2 hv = __half22float2(((const __half2*)g_h1)[(size_t)node * C2 + lane]);
    float2 bv = ((const float2*)b)[lane];
    float2 o;
    o.x = ax + hv.x * d2 + bv.x;
    o.y = ay + hv.y * d2 + bv.y;
    out[(size_t)node * C2 + lane] = o;
}

// -------- CSR gather layer 2 (F=32, fp16) + relu + classifier + log_softmax --
__global__ void k_gather32f(const float* __restrict__ b, const float* __restrict__ Wc,
                            const float* __restrict__ bc, float* __restrict__ outp,
                            int N) {
    constexpr int F = H2D;
    __shared__ float WcSm[H2D * NCLS];
    __shared__ float bcSm[NCLS];
    int tid = threadIdx.x;
    for (int i = tid; i < H2D * NCLS; i += blockDim.x) WcSm[i] = Wc[i];
    if (tid < NCLS) bcSm[tid] = bc[tid];
    __syncthreads();

    int node = blockIdx.x * (blockDim.x >> 5) + (tid >> 5);
    int lane = tid & 31;
    if (node >= N) return;

    const __half* h = g_h2;
    int beg = g_off[node];
    int end = g_off[node + 1];

    float acc = 0.0f;
    int j = beg;
    for (; j + 32 <= end; j += 32) {
        int2 m = __ldg(&g_edge[j + lane]);
#pragma unroll 8
        for (int k = 0; k < 32; k++) {
            int   s  = __shfl_sync(0xffffffffu, m.x, k);
            float nm = __int_as_float(__shfl_sync(0xffffffffu, m.y, k));
            acc += __half2float(__ldg(&h[(size_t)s * F + lane])) * nm;
        }
    }
    int rem = end - j;
    if (rem > 0) {
        int2 m = (lane < rem) ? __ldg(&g_edge[j + lane]) : make_int2(0, 0);
        for (int k = 0; k < rem; k++) {
            int   s  = __shfl_sync(0xffffffffu, m.x, k);
            float nm = __int_as_float(__shfl_sync(0xffffffffu, m.y, k));
            acc += __half2float(__ldg(&h[(size_t)s * F + lane])) * nm;
        }
    }

    float di = g_dinv[node];
    float x = acc + __half2float(h[(size_t)node * F + lane]) * di * di + b[lane];
    x = fmaxf(x, 0.0f);

    float p[NCLS];
#pragma unroll
    for (int c = 0; c < NCLS; c++) p[c] = x * WcSm[lane * NCLS + c];
#pragma unroll
    for (int s = 16; s > 0; s >>= 1)
#pragma unroll
        for (int c = 0; c < NCLS; c++)
            p[c] += __shfl_xor_sync(0xffffffffu, p[c], s);

    float lg[NCLS];
#pragma unroll
    for (int c = 0; c < NCLS; c++) lg[c] = p[c] + bcSm[c];
    float mx = lg[0];
#pragma unroll
    for (int c = 1; c < NCLS; c++) mx = fmaxf(mx, lg[c]);
    float sum = 0.0f;
#pragma unroll
    for (int c = 0; c < NCLS; c++) sum += __expf(lg[c] - mx);
    float lse = mx + logf(sum);

    if (lane < NCLS) outp[(size_t)node * NCLS + lane] = lg[lane] - lse;
}

// ---------------- launch (kernel launches ONLY; graph-capture clean) ---------
extern "C" void kernel_launch(void* const* d_in, const int* in_sizes, int n_in,
                              void* d_out, int out_size) {
    const float* feat = (const float*)d_in[0];
    const int*   ei   = (const int*)d_in[1];    // int32 (JAX x64 disabled)
    const float* W1   = (const float*)d_in[2];
    const float* b1   = (const float*)d_in[3];
    const float* W2   = (const float*)d_in[4];
    const float* b2   = (const float*)d_in[5];
    const float* Wc   = (const float*)d_in[6];
    const float* bc   = (const float*)d_in[7];

    int N = in_sizes[0] / FIN;
    int E = in_sizes[1] / 2;

    const int T = 256;
    int nb = (N + SCAN_B - 1) / SCAN_B;

    // CSR build (gemm1 at slot 4 so ncu profiles it)
    k_zero<<<(N + T - 1) / T, T>>>(N);
    k_count<<<(E + T - 1) / T, T>>>(ei, E);
    k_scan1<<<nb, SCAN_B>>>(N);
    k_gemm2x<FIN, H1D, false, 1, 8><<<(N + 255) / 256, 256>>>(feat, W1, N);  // #4
    k_scan2<<<1, 256>>>(nb);
    k_scan3<<<(N + T - 1) / T, T>>>(N, E);
    k_dinv<<<(N + T - 1) / T, T>>>(N);
    k_fill<<<(E + T - 1) / T, T>>>(ei, E);

    // layer 1 aggregation
    k_gather64<<<(N + 7) / 8, 256>>>(b1, N);

    // layer 2 + fused classifier/log_softmax
    k_gemm2x<H1D, H2D, true, 2, 4><<<(N + 255) / 256, 256>>>(nullptr, W2, N);
    k_gather32f<<<(N + 7) / 8, 256>>>(b2, Wc, bc, (float*)d_out, N);
}